// round 1
// baseline (speedup 1.0000x reference)
#include <cuda_runtime.h>
#include <math.h>
#include <float.h>

// ---------------- problem constants ----------------
#define Gg    2
#define NPn   332          // nodes per graph (stage 1)
#define NN    664          // total nodes
#define NE    21248        // edges
#define FD    332          // feature dim (INDIM = D1 = D2)
#define KHH   6            // pos-MLP bottleneck
#define KD    2324         // (KHH+1)*FD  : 6 channels + nb channel
#define KP1   166
#define KP2   83
#define ZDIM  1328         // (D1+D2)*2
#define DD3   128

// ---------------- scratch (static device globals; no runtime alloc) ------
__device__ float g_X7 [NN * KD];        // 6.2 MB
__device__ float g_B  [KD * FD];        // 3.1 MB staged [W2 ; nb]
__device__ float g_xt [NN * FD];        // GEMM output (per-node transformed feats)
__device__ float g_h1 [NN * FD];        // conv1 output
__device__ float g_hp1[Gg*KP1 * FD];    // pooled-1 features
__device__ float g_h2 [Gg*KP1 * FD];    // conv2 output
__device__ float g_hp2[Gg*KP2 * FD];    // pooled-2 features (readout src)
__device__ int   g_perm1 [Gg*KP1];
__device__ int   g_perm2 [Gg*KP2];
__device__ int   g_newidx1[NN];
__device__ int   g_newidx2[Gg*KP1];
__device__ int   g_csr_ptr[NN + 1];
__device__ int   g_csr_eid[NE];
__device__ int   g_csr_src[NE];
__device__ float g_z  [Gg * ZDIM];      // [max1|mean1|max2|mean2] per graph
__device__ float g_t1 [Gg * FD];
__device__ float g_t2 [Gg * DD3];

// ---------------- kernel 1: build X7 = [h6 (x) x | x] -------------------
// stage 0: x from param (conv1, 664 rows, pos row = node id)
// stage 1: x from g_hp1 (conv2, 332 rows, pos row = g_perm1[j])
__global__ void k_build_x7(const float* __restrict__ x_in,
                           const float* __restrict__ pos,
                           const float* __restrict__ W1, int stage)
{
    int j = blockIdx.x;
    int t = threadIdx.x;                 // 256 threads
    __shared__ float red[KHH * 256];
    __shared__ float h6s[KHH];
    const float* xr;
    const float* pr;
    if (stage == 0) { xr = x_in + (size_t)j * FD; pr = pos + (size_t)j * FD; }
    else            { xr = &g_hp1[(size_t)j * FD]; pr = pos + (size_t)g_perm1[j] * FD; }

    float p[KHH];
#pragma unroll
    for (int k = 0; k < KHH; k++) p[k] = 0.f;
    for (int i = t; i < FD; i += 256) {
        float pv = pr[i];
#pragma unroll
        for (int k = 0; k < KHH; k++) p[k] += pv * W1[i * KHH + k];
    }
#pragma unroll
    for (int k = 0; k < KHH; k++) red[k * 256 + t] = p[k];
    __syncthreads();
    for (int s = 128; s > 0; s >>= 1) {
        if (t < s) {
#pragma unroll
            for (int k = 0; k < KHH; k++) red[k * 256 + t] += red[k * 256 + t + s];
        }
        __syncthreads();
    }
    if (t < KHH) h6s[t] = fmaxf(red[t * 256], 0.f);   // relu
    __syncthreads();

    float* out = &g_X7[(size_t)j * KD];
    for (int c = t; c < KD; c += 256) {
        int k = c / FD;
        int i = c - k * FD;
        float hv = (k < KHH) ? h6s[k] : 1.f;          // channel 6 carries nb term
        out[c] = hv * xr[i];
    }
}

// ---------------- kernel 2: fp32 GEMM  C[M,332] = X7[M,2324] @ B --------
#define BM 32
#define BN 32
#define BK 16
__global__ void k_gemm(int M)
{
    __shared__ float As[BK][BM + 2];
    __shared__ float Bs[BK][BN + 2];
    int tid = threadIdx.x;               // 256
    int tx = tid & 15, ty = tid >> 4;
    int row0 = blockIdx.y * BM;
    int col0 = blockIdx.x * BN;
    float a00 = 0.f, a01 = 0.f, a10 = 0.f, a11 = 0.f;

    for (int k0 = 0; k0 < KD; k0 += BK) {
        for (int l = tid; l < BM * BK; l += 256) {
            int m = l >> 4, k = l & 15;
            int gr = row0 + m, gk = k0 + k;
            As[k][m] = (gr < M && gk < KD) ? g_X7[(size_t)gr * KD + gk] : 0.f;
        }
        for (int l = tid; l < BK * BN; l += 256) {
            int k = l >> 5, n = l & 31;
            int gk = k0 + k, gc = col0 + n;
            Bs[k][n] = (gk < KD && gc < FD) ? g_B[(size_t)gk * FD + gc] : 0.f;
        }
        __syncthreads();
#pragma unroll
        for (int kk = 0; kk < BK; kk++) {
            float av0 = As[kk][ty * 2], av1 = As[kk][ty * 2 + 1];
            float bv0 = Bs[kk][tx * 2], bv1 = Bs[kk][tx * 2 + 1];
            a00 += av0 * bv0; a01 += av0 * bv1;
            a10 += av1 * bv0; a11 += av1 * bv1;
        }
        __syncthreads();
    }
    int r = row0 + ty * 2, c = col0 + tx * 2;
    if (r < M) {
        if (c     < FD) g_xt[(size_t)r * FD + c]     = a00;
        if (c + 1 < FD) g_xt[(size_t)r * FD + c + 1] = a01;
    }
    if (r + 1 < M) {
        if (c     < FD) g_xt[(size_t)(r + 1) * FD + c]     = a10;
        if (c + 1 < FD) g_xt[(size_t)(r + 1) * FD + c + 1] = a11;
    }
}

// ---------------- kernel 3: CSR build (single block) --------------------
// stage 0: conv1 (all edges, ids direct). stage 1: conv2 (remap by g_newidx1,
// drop edges with either endpoint removed).
__global__ void k_csr(int n_dst, int stage, const int* __restrict__ ei)
{
    __shared__ int cnt[1024];
    __shared__ int base[1024];
    int t = threadIdx.x;                 // 1024 threads
    cnt[t] = 0;
    __syncthreads();
    const int* src = ei;
    const int* dst = ei + NE;

    for (int e = t; e < NE; e += 1024) {
        int nd;
        if (stage == 0) nd = dst[e];
        else {
            int ns = g_newidx1[src[e]];
            int n2 = g_newidx1[dst[e]];
            if (ns < 0 || n2 < 0) continue;
            nd = n2;
        }
        atomicAdd(&cnt[nd], 1);
    }
    __syncthreads();
    // inclusive scan over 1024 (zeros beyond n_dst)
    for (int off = 1; off < 1024; off <<= 1) {
        int v = (t >= off) ? cnt[t - off] : 0;
        __syncthreads();
        cnt[t] += v;
        __syncthreads();
    }
    if (t == 0) g_csr_ptr[0] = 0;
    if (t < n_dst) g_csr_ptr[t + 1] = cnt[t];
    int excl = (t == 0) ? 0 : cnt[t - 1];
    __syncthreads();
    base[t] = excl;
    cnt[t] = 0;
    __syncthreads();

    for (int e = t; e < NE; e += 1024) {
        int ns, nd;
        if (stage == 0) { ns = src[e]; nd = dst[e]; }
        else {
            ns = g_newidx1[src[e]];
            nd = g_newidx1[dst[e]];
            if (ns < 0 || nd < 0) continue;
        }
        int slot = atomicAdd(&cnt[nd], 1);
        int p = base[nd] + slot;
        g_csr_eid[p] = e;
        g_csr_src[p] = ns;
    }
}

// ---------------- kernel 4: per-dst softmax aggregation -----------------
// logits: edge_attr[e] for kept edges, 1.0 for self-loop. out = sum alpha*xt[src] + bias
__global__ void k_agg(int outsel, const float* __restrict__ eattr,
                      const float* __restrict__ bias)
{
    int d = blockIdx.x;
    int t = threadIdx.x;                 // 128
    int begin = g_csr_ptr[d], end = g_csr_ptr[d + 1];
    int deg = end - begin;
    __shared__ float sred[128];

    float m = 1.0f;                      // self-loop logit
    for (int e = begin + t; e < end; e += 128) m = fmaxf(m, eattr[g_csr_eid[e]]);
    sred[t] = m; __syncthreads();
    for (int s = 64; s > 0; s >>= 1) { if (t < s) sred[t] = fmaxf(sred[t], sred[t + s]); __syncthreads(); }
    m = sred[0]; __syncthreads();

    float se = 0.f;
    for (int e = begin + t; e < end; e += 128) se += expf(eattr[g_csr_eid[e]] - m);
    sred[t] = se; __syncthreads();
    for (int s = 64; s > 0; s >>= 1) { if (t < s) sred[t] += sred[t + s]; __syncthreads(); }
    float inv = 1.f / (sred[0] + expf(1.0f - m));
    float selfw = expf(1.0f - m) * inv;
    __syncthreads();

    __shared__ float ws[128];
    __shared__ int   ss[128];
    int o0 = t, o1 = t + 128, o2 = t + 256;
    const float* xd = &g_xt[(size_t)d * FD];
    float acc0 = selfw * xd[o0];
    float acc1 = selfw * xd[o1];
    float acc2 = (o2 < FD) ? selfw * xd[o2] : 0.f;

    for (int c0 = 0; c0 < deg; c0 += 128) {
        if (c0 + t < deg) {
            int e = begin + c0 + t;
            ws[t] = expf(eattr[g_csr_eid[e]] - m) * inv;
            ss[t] = g_csr_src[e];
        }
        __syncthreads();
        int cn = min(128, deg - c0);
        for (int q = 0; q < cn; q++) {
            float wv = ws[q];
            const float* xr = &g_xt[(size_t)ss[q] * FD];
            acc0 += wv * xr[o0];
            acc1 += wv * xr[o1];
            if (o2 < FD) acc2 += wv * xr[o2];
        }
        __syncthreads();
    }
    float* out = (outsel == 0) ? g_h1 : g_h2;
    out[(size_t)d * FD + o0] = acc0 + bias[o0];
    out[(size_t)d * FD + o1] = acc1 + bias[o1];
    if (o2 < FD) out[(size_t)d * FD + o2] = acc2 + bias[o2];
}

// ---------------- kernel 5: TopK pooling + readout (one block per graph) -
__global__ void k_pool(const float* __restrict__ w, int stage)
{
    int g = blockIdx.x;
    int t = threadIdx.x;                 // 512
    const float* h; int n_per, K; float* xnew; int* perm; int* newidx; int zoff;
    if (stage == 1) { h = g_h1; n_per = NPn; K = KP1; xnew = g_hp1; perm = g_perm1; newidx = g_newidx1; zoff = 0; }
    else            { h = g_h2; n_per = KP1; K = KP2; xnew = g_hp2; perm = g_perm2; newidx = g_newidx2; zoff = 2 * FD; }

    __shared__ float sw[FD];
    __shared__ float sred[512];
    __shared__ float sc[512];
    __shared__ int   si[512];

    for (int i = t; i < FD; i += 512) sw[i] = w[i];
    float p = 0.f;
    for (int i = t; i < FD; i += 512) p += w[i] * w[i];
    sred[t] = p; __syncthreads();
    for (int s = 256; s > 0; s >>= 1) { if (t < s) sred[t] += sred[t + s]; __syncthreads(); }
    float invn = rsqrtf(sred[0]);
    __syncthreads();

    if (t < n_per) {
        const float* hr = h + (size_t)(g * n_per + t) * FD;
        float dt = 0.f;
        for (int i = 0; i < FD; i++) dt += hr[i] * sw[i];
        float a = dt * invn;
        sc[t] = 1.f / (1.f + expf(-a));  // sigmoid
        si[t] = t;
    } else { sc[t] = -FLT_MAX; si[t] = 100000 + t; }
    __syncthreads();

    // bitonic sort, descending by score (tie: smaller index first)
    for (int k = 2; k <= 512; k <<= 1) {
        for (int j = k >> 1; j > 0; j >>= 1) {
            int ixj = t ^ j;
            if (ixj > t) {
                float a = sc[t], b = sc[ixj];
                int ia = si[t], ib = si[ixj];
                bool afirst = (a > b) || (a == b && ia < ib);
                bool up = ((t & k) == 0);
                bool dosw = up ? (!afirst) : afirst;
                if (dosw) { sc[t] = b; sc[ixj] = a; si[t] = ib; si[ixj] = ia; }
            }
            __syncthreads();
        }
    }

    if (si[t] < n_per) {
        int node = g * n_per + si[t];
        newidx[node] = (t < K) ? (g * K + t) : -1;
    }
    if (t < K) perm[g * K + t] = g * n_per + si[t];
    __syncthreads();

    // x_new = h[selected] * score (used as next conv input)
    for (int idx = t; idx < K * FD; idx += 512) {
        int r = idx / FD, i = idx - r * FD;
        xnew[(size_t)(g * K + r) * FD + i] =
            h[(size_t)(g * n_per + si[r]) * FD + i] * sc[r];
    }
    // readout (max / mean over the K kept, scaled rows)
    for (int i = t; i < FD; i += 512) {
        float mx = -FLT_MAX, sm = 0.f;
        for (int r = 0; r < K; r++) {
            float v = h[(size_t)(g * n_per + si[r]) * FD + i] * sc[r];
            mx = fmaxf(mx, v); sm += v;
        }
        g_z[g * ZDIM + zoff + i]      = mx;
        g_z[g * ZDIM + zoff + FD + i] = sm / (float)K;
    }
}

// ---------------- MLP head ----------------------------------------------
__global__ void k_fc(int insel, const float* __restrict__ W, const float* __restrict__ b,
                     int Kin, int Nout, int outsel, float* dout)
{
    int o = blockIdx.x;
    int t = threadIdx.x;                 // 128
    const float* in = (insel == 0) ? g_z : (insel == 1) ? g_t1 : g_t2;
    __shared__ float s0[128], s1[128];
    float a0 = 0.f, a1 = 0.f;
    for (int i = t; i < Kin; i += 128) {
        float wv = W[(size_t)i * Nout + o];
        a0 += in[i] * wv;
        a1 += in[Kin + i] * wv;
    }
    s0[t] = a0; s1[t] = a1; __syncthreads();
    for (int s = 64; s > 0; s >>= 1) { if (t < s) { s0[t] += s0[t + s]; s1[t] += s1[t + s]; } __syncthreads(); }
    if (t == 0) {
        float* out = (outsel == 0) ? g_t1 : (outsel == 1) ? g_t2 : dout;
        out[o]        = s0[0] + b[o];
        out[Nout + o] = s1[0] + b[o];
    }
}

__global__ void k_bn(int sel, const float* __restrict__ gm, const float* __restrict__ bt, int n)
{
    int o = threadIdx.x + blockIdx.x * blockDim.x;
    if (o >= n) return;
    float* a = (sel == 0) ? g_t1 : g_t2;
    float a0 = a[o], a1 = a[n + o];
    float mn = 0.5f * (a0 + a1);
    float v  = 0.5f * ((a0 - mn) * (a0 - mn) + (a1 - mn) * (a1 - mn));
    float is = rsqrtf(v + 1e-5f);
    a[o]     = fmaxf((a0 - mn) * is * gm[o] + bt[o], 0.f);
    a[n + o] = fmaxf((a1 - mn) * is * gm[o] + bt[o], 0.f);
}

// ---------------- launch -------------------------------------------------
extern "C" void kernel_launch(void* const* d_in, const int* in_sizes, int n_in,
                              void* d_out, int out_size)
{
    const float* x     = (const float*)d_in[0];
    const int*   ei    = (const int*)  d_in[1];
    const float* eattr = (const float*)d_in[3];
    const float* pos   = (const float*)d_in[4];
    const float* c1W1  = (const float*)d_in[6];
    const float* c1W2  = (const float*)d_in[7];
    const float* c1nb  = (const float*)d_in[8];
    const float* c1b   = (const float*)d_in[9];
    const float* p1w   = (const float*)d_in[10];
    const float* c2W1  = (const float*)d_in[11];
    const float* c2W2  = (const float*)d_in[12];
    const float* c2nb  = (const float*)d_in[13];
    const float* c2b   = (const float*)d_in[14];
    const float* p2w   = (const float*)d_in[15];
    const float* fc1W  = (const float*)d_in[16];
    const float* fc1b  = (const float*)d_in[17];
    const float* bn1g  = (const float*)d_in[18];
    const float* bn1b  = (const float*)d_in[19];
    const float* fc2W  = (const float*)d_in[20];
    const float* fc2b  = (const float*)d_in[21];
    const float* bn2g  = (const float*)d_in[22];
    const float* bn2b  = (const float*)d_in[23];
    const float* fc3W  = (const float*)d_in[24];
    const float* fc3b  = (const float*)d_in[25];
    float* out = (float*)d_out;

    const size_t w2bytes = (size_t)KHH * FD * FD * sizeof(float);
    const size_t nbbytes = (size_t)FD * FD * sizeof(float);

    // ---- conv1 ----
    cudaMemcpyToSymbolAsync(g_B, c1W2, w2bytes, 0,       cudaMemcpyDeviceToDevice, 0);
    cudaMemcpyToSymbolAsync(g_B, c1nb, nbbytes, w2bytes, cudaMemcpyDeviceToDevice, 0);
    k_build_x7<<<NN, 256>>>(x, pos, c1W1, 0);
    {
        dim3 g1((FD + BN - 1) / BN, (NN + BM - 1) / BM);
        k_gemm<<<g1, 256>>>(NN);
    }
    k_csr<<<1, 1024>>>(NN, 0, ei);
    k_agg<<<NN, 128>>>(0, eattr, c1b);
    // ---- pool1 + readout1 ----
    k_pool<<<Gg, 512>>>(p1w, 1);
    // ---- conv2 ----
    cudaMemcpyToSymbolAsync(g_B, c2W2, w2bytes, 0,       cudaMemcpyDeviceToDevice, 0);
    cudaMemcpyToSymbolAsync(g_B, c2nb, nbbytes, w2bytes, cudaMemcpyDeviceToDevice, 0);
    k_build_x7<<<Gg * KP1, 256>>>(x, pos, c2W1, 1);
    {
        dim3 g2((FD + BN - 1) / BN, (Gg * KP1 + BM - 1) / BM);
        k_gemm<<<g2, 256>>>(Gg * KP1);
    }
    k_csr<<<1, 1024>>>(Gg * KP1, 1, ei);
    k_agg<<<Gg * KP1, 128>>>(1, eattr, c2b);
    // ---- pool2 + readout2 ----
    k_pool<<<Gg, 512>>>(p2w, 2);
    // ---- MLP head ----
    k_fc<<<FD, 128>>>(0, fc1W, fc1b, ZDIM, FD, 0, nullptr);
    k_bn<<<(FD + 127) / 128, 128>>>(0, bn1g, bn1b, FD);
    k_fc<<<DD3, 128>>>(1, fc2W, fc2b, FD, DD3, 1, nullptr);
    k_bn<<<1, 128>>>(1, bn2g, bn2b, DD3);
    k_fc<<<2, 128>>>(2, fc3W, fc3b, DD3, 2, 2, out);
}

// round 2
// speedup vs baseline: 1.5525x; 1.5525x over previous
#include <cuda_runtime.h>
#include <math.h>
#include <float.h>

// ---------------- problem constants ----------------
#define Gg    2
#define NPn   332
#define NN    664
#define NE    21248
#define FD    332
#define KD    2324          // 7*FD : 6 W2 slices + nb
#define W2SZ  (FD*FD)
#define KP1   166
#define KP2   83
#define ZDIM  1328
#define DD3   128

// ---------------- scratch ----------------
__device__ float g_h6 [NN * 8];
__device__ float g_xt [NN * FD];
__device__ float g_h1 [NN * FD];
__device__ float g_hp1[Gg*KP1 * FD];
__device__ float g_h2 [Gg*KP1 * FD];
__device__ float g_score[NN];
__device__ int   g_perm1 [Gg*KP1];
__device__ int   g_newidx1[NN];
__device__ int   g_csr_ptr[NN + 1];
__device__ int   g_csr_eid[NE];
__device__ int   g_csr_src[NE];
__device__ float g_z  [Gg * ZDIM];

// ---------------- h6 = relu(pos @ W1), one warp per node ----------------
__global__ void k_h6(const float* __restrict__ pos, const float* __restrict__ W1)
{
    int w = threadIdx.x >> 5, lane = threadIdx.x & 31;
    int j = blockIdx.x * 8 + w;
    if (j >= NN) return;
    float p[6] = {0.f,0.f,0.f,0.f,0.f,0.f};
    const float* pr = pos + (size_t)j * FD;
    for (int i = lane; i < FD; i += 32) {
        float pv = pr[i];
#pragma unroll
        for (int k = 0; k < 6; k++) p[k] += pv * W1[i*6 + k];
    }
#pragma unroll
    for (int off = 16; off; off >>= 1) {
#pragma unroll
        for (int k = 0; k < 6; k++) p[k] += __shfl_down_sync(0xffffffffu, p[k], off);
    }
    if (lane == 0) {
#pragma unroll
        for (int k = 0; k < 6; k++) g_h6[j*8 + k] = fmaxf(p[k], 0.f);
        g_h6[j*8 + 6] = 1.f;
        g_h6[j*8 + 7] = 0.f;
    }
}

// ---------------- GEMM: g_xt[M,332] = Ascaled[M,2324] @ [W2;nb] ---------
// A[m, k*332+i] = X[m,i] * h6[m,k]   (h6[:,6]=1 carries the nb term)
template<int BM>
__global__ void __launch_bounds__(256) k_gemm(int stage, const float* __restrict__ Xext,
        int M, const float* __restrict__ W2, const float* __restrict__ nb)
{
    constexpr int BN = 64, BK = 16;
    constexpr int RM = BM / 16;
    __shared__ float As[2][BK][BM + 4];
    __shared__ float Bs[2][BK][BN + 4];
    const float* X = stage ? (const float*)g_hp1 : Xext;
    const int tid = threadIdx.x;
    const int tx = tid & 15, ty = tid >> 4;
    const int row0 = blockIdx.y * BM, col0 = blockIdx.x * BN;
    float acc[RM][4];
#pragma unroll
    for (int j = 0; j < RM; j++) { acc[j][0]=0.f; acc[j][1]=0.f; acc[j][2]=0.f; acc[j][3]=0.f; }
    const int NCH = (KD + BK - 1) / BK;

    auto load_tile = [&](int c, int b) {
#pragma unroll
        for (int i = 0; i < (BM*BK)/256; i++) {
            int l = tid + i*256;
            int m = l >> 4, k = l & 15;
            int r = row0 + m, kg = c*BK + k;
            float v = 0.f;
            if (r < M && kg < KD) {
                int kk = kg / FD, ki = kg - kk*FD;
                v = X[(size_t)r*FD + ki] * g_h6[r*8 + kk];
            }
            As[b][k][m] = v;
        }
        int k = tid >> 4, n = (tid & 15) << 2;
        int kg = c*BK + k, col = col0 + n;
        float4 v = make_float4(0.f,0.f,0.f,0.f);
        if (kg < KD && col < FD) {
            int kk = kg / FD, ki = kg - kk*FD;
            const float* bp = (kk < 6) ? (W2 + (size_t)kk*W2SZ) : nb;
            v = *(const float4*)(bp + (size_t)ki*FD + col);
        }
        *(float4*)&Bs[b][k][n] = v;
    };

    load_tile(0, 0);
    __syncthreads();
    for (int c = 0; c < NCH; c++) {
        int b = c & 1;
        if (c + 1 < NCH) load_tile(c + 1, b ^ 1);
#pragma unroll
        for (int kk = 0; kk < BK; kk++) {
            float4 bv = *(const float4*)&Bs[b][kk][tx << 2];
#pragma unroll
            for (int j = 0; j < RM; j++) {
                float av = As[b][kk][ty*RM + j];
                acc[j][0] += av*bv.x; acc[j][1] += av*bv.y;
                acc[j][2] += av*bv.z; acc[j][3] += av*bv.w;
            }
        }
        __syncthreads();
    }
    int col = col0 + (tx << 2);
    if (col < FD) {
#pragma unroll
        for (int j = 0; j < RM; j++) {
            int r = row0 + ty*RM + j;
            if (r < M)
                *(float4*)&g_xt[(size_t)r*FD + col] =
                    make_float4(acc[j][0], acc[j][1], acc[j][2], acc[j][3]);
        }
    }
}

// ---------------- CSR build (single block) ------------------------------
__global__ void k_csr(int n_dst, int stage, const int* __restrict__ ei)
{
    __shared__ int cnt[1024];
    __shared__ int base[1024];
    int t = threadIdx.x;
    cnt[t] = 0;
    __syncthreads();
    const int* src = ei;
    const int* dst = ei + NE;

    for (int e = t; e < NE; e += 1024) {
        int nd;
        if (stage == 0) nd = dst[e];
        else {
            int ns = g_newidx1[src[e]];
            int n2 = g_newidx1[dst[e]];
            if (ns < 0 || n2 < 0) continue;
            nd = n2;
        }
        atomicAdd(&cnt[nd], 1);
    }
    __syncthreads();
    for (int off = 1; off < 1024; off <<= 1) {
        int v = (t >= off) ? cnt[t - off] : 0;
        __syncthreads();
        cnt[t] += v;
        __syncthreads();
    }
    if (t == 0) g_csr_ptr[0] = 0;
    if (t < n_dst) g_csr_ptr[t + 1] = cnt[t];
    int excl = (t == 0) ? 0 : cnt[t - 1];
    __syncthreads();
    base[t] = excl;
    cnt[t] = 0;
    __syncthreads();

    for (int e = t; e < NE; e += 1024) {
        int ns, nd;
        if (stage == 0) { ns = src[e]; nd = dst[e]; }
        else {
            ns = g_newidx1[src[e]];
            nd = g_newidx1[dst[e]];
            if (ns < 0 || nd < 0) continue;
        }
        int slot = atomicAdd(&cnt[nd], 1);
        int p = base[nd] + slot;
        g_csr_eid[p] = e;
        g_csr_src[p] = ns;
    }
}

// ---------------- softmax aggregation + fused TopK score ----------------
__global__ void k_agg(int outsel, const float* __restrict__ eattr,
                      const float* __restrict__ bias, const float* __restrict__ pw)
{
    int d = blockIdx.x;
    int t = threadIdx.x;                 // 128
    __shared__ float sred[128];
    __shared__ float ws[128];
    __shared__ int   ss[128];

    // ||w||^2 for score normalization
    float ww = 0.f;
    for (int i = t; i < FD; i += 128) ww += pw[i] * pw[i];
    sred[t] = ww; __syncthreads();
    for (int s = 64; s; s >>= 1) { if (t < s) sred[t] += sred[t + s]; __syncthreads(); }
    float invn = rsqrtf(sred[0]);
    __syncthreads();

    int begin = g_csr_ptr[d], end = g_csr_ptr[d + 1];
    int deg = end - begin;

    float m = 1.0f;                      // self-loop logit
    for (int e = begin + t; e < end; e += 128) m = fmaxf(m, eattr[g_csr_eid[e]]);
    sred[t] = m; __syncthreads();
    for (int s = 64; s; s >>= 1) { if (t < s) sred[t] = fmaxf(sred[t], sred[t + s]); __syncthreads(); }
    m = sred[0]; __syncthreads();

    float se = 0.f;
    for (int e = begin + t; e < end; e += 128) se += expf(eattr[g_csr_eid[e]] - m);
    sred[t] = se; __syncthreads();
    for (int s = 64; s; s >>= 1) { if (t < s) sred[t] += sred[t + s]; __syncthreads(); }
    float selfe = expf(1.0f - m);
    float inv = 1.f / (sred[0] + selfe);
    float selfw = selfe * inv;
    __syncthreads();

    const float* xd = &g_xt[(size_t)d * FD];
    int o0 = t, o1 = t + 128, o2 = t + 256;
    float acc0 = selfw * xd[o0];
    float acc1 = selfw * xd[o1];
    float acc2 = (o2 < FD) ? selfw * xd[o2] : 0.f;

    for (int c0 = 0; c0 < deg; c0 += 128) {
        if (c0 + t < deg) {
            int e = begin + c0 + t;
            ws[t] = expf(eattr[g_csr_eid[e]] - m) * inv;
            ss[t] = g_csr_src[e];
        }
        __syncthreads();
        int cn = min(128, deg - c0);
        int q = 0;
        for (; q + 4 <= cn; q += 4) {
            const float* x0 = &g_xt[(size_t)ss[q]   * FD];
            const float* x1 = &g_xt[(size_t)ss[q+1] * FD];
            const float* x2 = &g_xt[(size_t)ss[q+2] * FD];
            const float* x3 = &g_xt[(size_t)ss[q+3] * FD];
            float w0 = ws[q], w1 = ws[q+1], w2 = ws[q+2], w3 = ws[q+3];
            acc0 += w0*x0[o0] + w1*x1[o0] + w2*x2[o0] + w3*x3[o0];
            acc1 += w0*x0[o1] + w1*x1[o1] + w2*x2[o1] + w3*x3[o1];
            if (o2 < FD) acc2 += w0*x0[o2] + w1*x1[o2] + w2*x2[o2] + w3*x3[o2];
        }
        for (; q < cn; q++) {
            float wv = ws[q];
            const float* xr = &g_xt[(size_t)ss[q] * FD];
            acc0 += wv * xr[o0];
            acc1 += wv * xr[o1];
            if (o2 < FD) acc2 += wv * xr[o2];
        }
        __syncthreads();
    }
    acc0 += bias[o0]; acc1 += bias[o1];
    if (o2 < FD) acc2 += bias[o2];
    float* out = outsel ? g_h2 : g_h1;
    out[(size_t)d * FD + o0] = acc0;
    out[(size_t)d * FD + o1] = acc1;
    if (o2 < FD) out[(size_t)d * FD + o2] = acc2;

    // fused TopK score: sigmoid((h . w) / ||w||)
    float dp = acc0 * pw[o0] + acc1 * pw[o1] + ((o2 < FD) ? acc2 * pw[o2] : 0.f);
    sred[t] = dp; __syncthreads();
    for (int s = 64; s; s >>= 1) { if (t < s) sred[t] += sred[t + s]; __syncthreads(); }
    if (t == 0) g_score[d] = 1.f / (1.f + expf(-sred[0] * invn));
}

// ---------------- TopK pool + readout + (stage1) next-conv h6 -----------
__global__ void k_pool(int stage, const float* __restrict__ pos, const float* __restrict__ W1)
{
    int g = blockIdx.x;
    int t = threadIdx.x;                 // 512
    const float* h; int n_per, K; float* xnew; int zoff;
    if (stage == 1) { h = g_h1; n_per = NPn; K = KP1; xnew = g_hp1; zoff = 0; }
    else            { h = g_h2; n_per = KP1; K = KP2; xnew = nullptr; zoff = 2 * FD; }

    __shared__ float sc[512];
    __shared__ int   si[512];
    if (t < n_per) { sc[t] = g_score[g * n_per + t]; si[t] = t; }
    else           { sc[t] = -FLT_MAX; si[t] = 100000 + t; }
    __syncthreads();

    for (int k = 2; k <= 512; k <<= 1) {
        for (int j = k >> 1; j; j >>= 1) {
            int ixj = t ^ j;
            if (ixj > t) {
                float a = sc[t], b2 = sc[ixj];
                int ia = si[t], ib = si[ixj];
                bool afirst = (a > b2) || (a == b2 && ia < ib);
                bool up = ((t & k) == 0);
                if (up ? !afirst : afirst) { sc[t] = b2; sc[ixj] = a; si[t] = ib; si[ixj] = ia; }
            }
            __syncthreads();
        }
    }

    if (stage == 1) {
        if (si[t] < n_per) g_newidx1[g * n_per + si[t]] = (t < K) ? (g * K + t) : -1;
        if (t < K) g_perm1[g * K + t] = g * n_per + si[t];
    }
    __syncthreads();

    if (stage == 1) {
        for (int idx = t; idx < K * FD; idx += 512) {
            int r = idx / FD, i = idx - r * FD;
            xnew[(size_t)(g * K + r) * FD + i] =
                h[(size_t)(g * n_per + si[r]) * FD + i] * sc[r];
        }
    }
    // readout: max / mean over kept scaled rows
    for (int i = t; i < FD; i += 512) {
        float mx = -FLT_MAX, sm = 0.f;
        for (int r = 0; r < K; r++) {
            float v = h[(size_t)(g * n_per + si[r]) * FD + i] * sc[r];
            mx = fmaxf(mx, v); sm += v;
        }
        g_z[g * ZDIM + zoff + i]      = mx;
        g_z[g * ZDIM + zoff + FD + i] = sm / (float)K;
    }
    // fused h6 for conv2 (pos rows of kept nodes)
    if (stage == 1) {
        for (int idx = t; idx < K * 6; idx += 512) {
            int r = idx / 6, k = idx - r * 6;
            const float* pr = pos + (size_t)(g * n_per + si[r]) * FD;
            float s = 0.f;
            for (int i = 0; i < FD; i++) s += pr[i] * W1[i*6 + k];
            g_h6[(size_t)(g * K + r) * 8 + k] = fmaxf(s, 0.f);
        }
        for (int idx = t; idx < K; idx += 512) {
            g_h6[(size_t)(g * K + idx) * 8 + 6] = 1.f;
            g_h6[(size_t)(g * K + idx) * 8 + 7] = 0.f;
        }
    }
}

// ---------------- fused MLP head (single block) -------------------------
__global__ void k_head(const float* __restrict__ fc1W, const float* __restrict__ fc1b,
                       const float* __restrict__ bn1g, const float* __restrict__ bn1b,
                       const float* __restrict__ fc2W, const float* __restrict__ fc2b,
                       const float* __restrict__ bn2g, const float* __restrict__ bn2b,
                       const float* __restrict__ fc3W, const float* __restrict__ fc3b,
                       float* __restrict__ out)
{
    int t = threadIdx.x;                 // 352
    __shared__ float sz[2 * ZDIM];
    __shared__ float s1[2 * FD];
    __shared__ float s2[2 * DD3];
    for (int i = t; i < 2 * ZDIM; i += 352) sz[i] = g_z[i];
    __syncthreads();

    if (t < FD) {
        float a0 = 0.f, a1 = 0.f;
        for (int i = 0; i < ZDIM; i++) {
            float wv = fc1W[(size_t)i * FD + t];
            a0 += sz[i] * wv;
            a1 += sz[ZDIM + i] * wv;
        }
        a0 += fc1b[t]; a1 += fc1b[t];
        float mn = 0.5f * (a0 + a1);
        float v  = 0.5f * ((a0 - mn)*(a0 - mn) + (a1 - mn)*(a1 - mn));
        float is = rsqrtf(v + 1e-5f);
        s1[t]      = fmaxf((a0 - mn) * is * bn1g[t] + bn1b[t], 0.f);
        s1[FD + t] = fmaxf((a1 - mn) * is * bn1g[t] + bn1b[t], 0.f);
    }
    __syncthreads();
    if (t < DD3) {
        float a0 = 0.f, a1 = 0.f;
        for (int i = 0; i < FD; i++) {
            float wv = fc2W[(size_t)i * DD3 + t];
            a0 += s1[i] * wv;
            a1 += s1[FD + i] * wv;
        }
        a0 += fc2b[t]; a1 += fc2b[t];
        float mn = 0.5f * (a0 + a1);
        float v  = 0.5f * ((a0 - mn)*(a0 - mn) + (a1 - mn)*(a1 - mn));
        float is = rsqrtf(v + 1e-5f);
        s2[t]       = fmaxf((a0 - mn) * is * bn2g[t] + bn2b[t], 0.f);
        s2[DD3 + t] = fmaxf((a1 - mn) * is * bn2g[t] + bn2b[t], 0.f);
    }
    __syncthreads();
    if (t < 2) {
        float a0 = 0.f, a1 = 0.f;
        for (int i = 0; i < DD3; i++) {
            float wv = fc3W[i*2 + t];
            a0 += s2[i] * wv;
            a1 += s2[DD3 + i] * wv;
        }
        out[t]     = a0 + fc3b[t];
        out[2 + t] = a1 + fc3b[t];
    }
}

// ---------------- launch -------------------------------------------------
extern "C" void kernel_launch(void* const* d_in, const int* in_sizes, int n_in,
                              void* d_out, int out_size)
{
    const float* x     = (const float*)d_in[0];
    const int*   ei    = (const int*)  d_in[1];
    const float* eattr = (const float*)d_in[3];
    const float* pos   = (const float*)d_in[4];
    const float* c1W1  = (const float*)d_in[6];
    const float* c1W2  = (const float*)d_in[7];
    const float* c1nb  = (const float*)d_in[8];
    const float* c1b   = (const float*)d_in[9];
    const float* p1w   = (const float*)d_in[10];
    const float* c2W1  = (const float*)d_in[11];
    const float* c2W2  = (const float*)d_in[12];
    const float* c2nb  = (const float*)d_in[13];
    const float* c2b   = (const float*)d_in[14];
    const float* p2w   = (const float*)d_in[15];
    const float* fc1W  = (const float*)d_in[16];
    const float* fc1b  = (const float*)d_in[17];
    const float* bn1g  = (const float*)d_in[18];
    const float* bn1b  = (const float*)d_in[19];
    const float* fc2W  = (const float*)d_in[20];
    const float* fc2b  = (const float*)d_in[21];
    const float* bn2g  = (const float*)d_in[22];
    const float* bn2b  = (const float*)d_in[23];
    const float* fc3W  = (const float*)d_in[24];
    const float* fc3b  = (const float*)d_in[25];
    float* out = (float*)d_out;

    // conv1
    k_h6 <<<(NN + 7) / 8, 256>>>(pos, c1W1);
    k_gemm<32><<<dim3(6, (NN + 31) / 32), 256>>>(0, x, NN, c1W2, c1nb);
    k_csr <<<1, 1024>>>(NN, 0, ei);
    k_agg <<<NN, 128>>>(0, eattr, c1b, p1w);
    // pool1 + readout1 + conv2 h6
    k_pool<<<Gg, 512>>>(1, pos, c2W1);
    // conv2
    k_gemm<16><<<dim3(6, (Gg * KP1 + 15) / 16), 256>>>(1, x, Gg * KP1, c2W2, c2nb);
    k_csr <<<1, 1024>>>(Gg * KP1, 1, ei);
    k_agg <<<Gg * KP1, 128>>>(1, eattr, c2b, p2w);
    // pool2 + readout2
    k_pool<<<Gg, 512>>>(2, nullptr, nullptr);
    // head
    k_head<<<1, 352>>>(fc1W, fc1b, bn1g, bn1b, fc2W, fc2b, bn2g, bn2b, fc3W, fc3b, out);
}